// round 16
// baseline (speedup 1.0000x reference)
#include <cuda_runtime.h>
#include <math.h>
#include <stdint.h>

// ---------------- problem constants ----------------
#define Bn   8
#define Cc   256
#define Hh   128
#define Ww   128
#define HWc  16384
#define MIDc 128
#define RMIDc 64
#define Kk   5
#define THRf   0.1f
#define SMINf  0.05f
#define SMAXf  0.45f
#define BETAf  1.5f
#define DMAXf  0.08f
#define RMINf  0.03f
#define RMAXf  0.4f
#define PIf    3.14159265358979323846f
#define BNSCALE 0.99999500003749971f

// ---------------- scratch ----------------
__device__ __align__(16) float g_t  [(size_t)Bn * Cc   * HWc];
__device__ __align__(16) float g_t2 [(size_t)Bn * Cc   * HWc];
__device__ __align__(16) float g_h1 [(size_t)Bn * MIDc * HWc];
__device__ __align__(16) float g_rmap[Bn * HWc];
__device__ __align__(16) float g_peaks[Bn * HWc];
__device__ __align__(16) float g_centers[Bn * Kk * 3];
__device__ __align__(16) float g_params [Bn * Kk * 8];
// fragment-swizzled, tf32-rounded weights
__device__ __align__(16) float g_w1c[MIDc * Cc];
__device__ __align__(16) float g_w3c[MIDc * MIDc * 9];
__device__ __align__(16) float g_wrc[RMIDc * Cc];

__device__ __forceinline__ uint32_t f2tf32(float x) {
    uint32_t r;
    asm("cvt.rna.tf32.f32 %0, %1;" : "=r"(r) : "f"(x));
    return r;
}
__device__ __forceinline__ float f2tf32f(float x) { return __uint_as_float(f2tf32(x)); }

__device__ __forceinline__ void mma_tf32(float c[4],
                                         uint32_t a0, uint32_t a1, uint32_t a2, uint32_t a3,
                                         uint32_t b0, uint32_t b1) {
    asm volatile(
        "mma.sync.aligned.m16n8k8.row.col.f32.tf32.tf32.f32 "
        "{%0,%1,%2,%3}, {%4,%5,%6,%7}, {%8,%9}, {%0,%1,%2,%3};\n"
        : "+f"(c[0]), "+f"(c[1]), "+f"(c[2]), "+f"(c[3])
        : "r"(a0), "r"(a1), "r"(a2), "r"(a3), "r"(b0), "r"(b1));
}

__device__ __forceinline__ void cp16(uint32_t dst, const void* src) {
    asm volatile("cp.async.cg.shared.global [%0], [%1], 16;\n" :: "r"(dst), "l"(src));
}
__device__ __forceinline__ void cp4(uint32_t dst, const void* src, int sz) {
    asm volatile("cp.async.ca.shared.global [%0], [%1], 4, %2;\n"
                 :: "r"(dst), "l"(src), "r"(sz));
}
#define CP_COMMIT() asm volatile("cp.async.commit_group;\n" ::: "memory")
template<int N> __device__ __forceinline__ void cp_wait() {
    asm volatile("cp.async.wait_group %0;\n" :: "n"(N) : "memory");
}

// ================= weight swizzle: fragment-ready layout, tf32-rounded =================
__global__ void swizzleA(const float* __restrict__ src, float* __restrict__ dst,
                         int M, int K, int MB, int conv)
{
    int i = blockIdx.x * 256 + threadIdx.x;
    if (i >= M * K) return;
    int q    = i & 3;
    int lane = (i >> 2) & 31;
    int kh   = (i >> 7) & 1;
    int rest = i >> 8;
    int mb   = rest % MB;
    int kt   = rest / MB;
    int m  = mb * 16 + (lane >> 2) + (q & 1) * 8;
    int k  = kt * 16 + kh * 8 + (lane & 3) + ((q >> 1) << 2);
    int sc = conv ? ((k & 127) * 9 + (k >> 7)) : k;
    dst[i] = f2tf32f(src[(size_t)m * K + sc]);
}

// ================= fused dual depthwise 3x3 (pad=1): register-sliding float4 =====
// One CTA per (b,c) plane; 8 warps x 16 rows; lane owns 4 cols (float4).
struct DwRow { float4 m, l, r; };

__global__ __launch_bounds__(256)
void dw3x3_dual(const float* __restrict__ in,
                const float* __restrict__ w1,
                const float* __restrict__ w2,
                float* __restrict__ out1,
                float* __restrict__ out2)
{
    int zc = blockIdx.x;                // b*C + c
    int c  = zc & (Cc - 1);
    const float4* inp = (const float4*)(in   + (size_t)zc * HWc);
    float4*       o1  = (float4*)      (out1 + (size_t)zc * HWc);
    float4*       o2  = (float4*)      (out2 + (size_t)zc * HWc);

    int lane = threadIdx.x & 31, w = threadIdx.x >> 5;
    int y0 = w * 16;

    float wa[9], wb[9];
    #pragma unroll
    for (int i = 0; i < 9; i++) { wa[i] = w1[c*9+i]; wb[i] = w2[c*9+i]; }

    auto loadrow = [&](int y) -> DwRow {
        DwRow R;
        if ((unsigned)y < (unsigned)Hh) R.m = inp[y * 32 + lane];
        else R.m = make_float4(0.f, 0.f, 0.f, 0.f);
        float lx = __shfl_up_sync(0xffffffffu, R.m.w, 1);
        float rx = __shfl_down_sync(0xffffffffu, R.m.x, 1);
        if (lane == 0)  lx = 0.f;
        if (lane == 31) rx = 0.f;
        R.l = make_float4(lx, R.m.x, R.m.y, R.m.z);
        R.r = make_float4(R.m.y, R.m.z, R.m.w, rx);
        return R;
    };

    DwRow rp = loadrow(y0 - 1);
    DwRow rc = loadrow(y0);

    #pragma unroll 4
    for (int y = y0; y < y0 + 16; y++) {
        DwRow rn = loadrow(y + 1);

        float4 s1, s2;
        #define CONV_C(dst, W, CMP) \
            dst.CMP = W[0]*rp.l.CMP + W[1]*rp.m.CMP + W[2]*rp.r.CMP \
                    + W[3]*rc.l.CMP + W[4]*rc.m.CMP + W[5]*rc.r.CMP \
                    + W[6]*rn.l.CMP + W[7]*rn.m.CMP + W[8]*rn.r.CMP;
        CONV_C(s1, wa, x) CONV_C(s1, wa, y) CONV_C(s1, wa, z) CONV_C(s1, wa, w)
        CONV_C(s2, wb, x) CONV_C(s2, wb, y) CONV_C(s2, wb, z) CONV_C(s2, wb, w)
        #undef CONV_C

        float4 t1 = make_float4(f2tf32f(s1.x), f2tf32f(s1.y), f2tf32f(s1.z), f2tf32f(s1.w));
        float4 t2 = make_float4(f2tf32f(s2.x), f2tf32f(s2.y), f2tf32f(s2.z), f2tf32f(s2.w));
        o1[y * 32 + lane] = t1;
        o2[y * 32 + lane] = t2;

        rp = rc; rc = rn;
    }
}

// ================= TF32 tensor-core GEMM, 4-stage cp.async, fragment-swizzled A =====
// HEAD 0: write full (M, HW) matrix (BN+ReLU, opt tf32-round)
// HEAD 1: fused heat head   -> out[b*2HW + HW + n] = sigmoid(sum_m hw[m]*relu(bn))+...
// HEAD 2: fused radius head -> out[b*HW + n] = RMIN + sigmoid(.)*(RMAX-RMIN)
#define BST 136
#define B_W (16 * BST)
#define NSTAGE 4

template<int MODE, int TI, int TJ, int WROWS, bool ROUND_OUT, int AW, int HEAD>
__global__ __launch_bounds__(256, 2)
void mma_gemm(const float* __restrict__ in,
              const float* __restrict__ wA,
              const float* __restrict__ gamma,
              const float* __restrict__ beta,
              const float* __restrict__ hw,
              const float* __restrict__ hb,
              float* __restrict__ out,
              int M, int Kdim, int Cin)
{
    extern __shared__ float sm[];
    float* smA = sm;
    float* smB = sm + NSTAGE * AW;
    uint32_t smA_addr = (uint32_t)__cvta_generic_to_shared(smA);
    uint32_t smB_addr = (uint32_t)__cvta_generic_to_shared(smB);

    const int WCOLS = 8 / WROWS;

    int b  = blockIdx.z;
    int n0 = blockIdx.x * 128;
    int y  = blockIdx.x;                  // MODE 1: image row
    const float* inb = in + (size_t)b * Cin * HWc;

    int t = threadIdx.x;
    int lane = t & 31, w = t >> 5;
    int wrow = w / WCOLS, wcol = w % WCOLS;
    int mb0 = wrow * TI;
    int nwb = wcol * (TJ * 8);
    int gid = lane >> 2, tig = lane & 3;

    int nl = t & 127, kb = t >> 7;        // MODE1 B
    int kB = t >> 5, ngB = t & 31;        // MODE0 B

    float acc[TI][TJ][4];
    #pragma unroll
    for (int i = 0; i < TI; i++)
        #pragma unroll
        for (int j = 0; j < TJ; j++)
            #pragma unroll
            for (int q = 0; q < 4; q++) acc[i][j][q] = 0.f;

    int KT = Kdim / 16;

    auto load_stage = [&](int st, int kt) {
        #pragma unroll
        for (int c = 0; c < AW / 4 / 256; c++) {
            int ch = t + c * 256;
            cp16(smA_addr + (uint32_t)(st * AW + ch * 4) * 4u, wA + (size_t)kt * AW + ch * 4);
        }
        if (MODE == 0) {
            int k0 = kt * 16;
            #pragma unroll
            for (int jj = 0; jj < 2; jj++) {
                int k = kB + jj * 8;
                cp16(smB_addr + (uint32_t)(st * B_W + k * BST + ngB * 4) * 4u,
                     inb + (size_t)(k0 + k) * HWc + n0 + ngB * 4);
            }
        } else {
            int tp  = kt >> 3;
            int dy  = tp / 3;
            int dx  = tp - dy * 3;
            int ci0 = (kt & 7) * 16;
            int yy  = y + dy - 1;
            int xx  = nl + dx - 1;
            bool ok = ((unsigned)yy < (unsigned)Hh) && ((unsigned)xx < (unsigned)Ww);
            const float* src = inb + (size_t)(ci0 + kb * 8) * HWc
                             + (ok ? (yy * Ww + xx) : 0);
            uint32_t dst = smB_addr + (uint32_t)(st * B_W + kb * 8 * BST + nl) * 4u;
            int sz = ok ? 4 : 0;
            #pragma unroll
            for (int j = 0; j < 8; j++)
                cp4(dst + (uint32_t)(j * BST) * 4u, src + (size_t)j * HWc, sz);
        }
    };

    auto compute = [&](int st) {
        const uint4*    A  = (const uint4*)(smA + st * AW);
        const uint32_t* Bq = (const uint32_t*)smB + st * B_W;
        #pragma unroll
        for (int kh = 0; kh < 2; kh++) {
            uint4 a[TI];
            #pragma unroll
            for (int ti = 0; ti < TI; ti++)
                a[ti] = A[((mb0 + ti) * 2 + kh) * 32 + lane];
            uint32_t bf[TJ][2];
            #pragma unroll
            for (int tj = 0; tj < TJ; tj++) {
                int nn = nwb + tj * 8 + gid;
                bf[tj][0] = Bq[(kh * 8 + tig    ) * BST + nn];
                bf[tj][1] = Bq[(kh * 8 + tig + 4) * BST + nn];
            }
            #pragma unroll
            for (int ti = 0; ti < TI; ti++)
                #pragma unroll
                for (int tj = 0; tj < TJ; tj++)
                    mma_tf32(acc[ti][tj], a[ti].x, a[ti].y, a[ti].z, a[ti].w,
                             bf[tj][0], bf[tj][1]);
        }
    };

    load_stage(0, 0); CP_COMMIT();
    load_stage(1, 1); CP_COMMIT();
    load_stage(2, 2); CP_COMMIT();

    for (int kt = 0; kt < KT; kt++) {
        cp_wait<2>();
        __syncthreads();
        if (kt + 3 < KT) load_stage((kt + 3) & 3, kt + 3);
        CP_COMMIT();
        compute(kt & 3);
    }

    if (HEAD == 0) {
        // ---- epilogue: BN + ReLU, write fp32 matrix ----
        float* outb = out + (size_t)b * M * HWc;
        #pragma unroll
        for (int ti = 0; ti < TI; ti++) {
            int m  = (mb0 + ti) * 16 + gid;
            int m2 = m + 8;
            float sc  = gamma[m ] * BNSCALE, bi  = beta[m ];
            float sc2 = gamma[m2] * BNSCALE, bi2 = beta[m2];
            #pragma unroll
            for (int tj = 0; tj < TJ; tj++) {
                int nn = n0 + nwb + tj * 8 + tig * 2;
                float2 v;
                v.x = fmaxf(acc[ti][tj][0] * sc + bi, 0.f);
                v.y = fmaxf(acc[ti][tj][1] * sc + bi, 0.f);
                if (ROUND_OUT) { v.x = f2tf32f(v.x); v.y = f2tf32f(v.y); }
                *(float2*)&outb[(size_t)m * HWc + nn] = v;
                v.x = fmaxf(acc[ti][tj][2] * sc2 + bi2, 0.f);
                v.y = fmaxf(acc[ti][tj][3] * sc2 + bi2, 0.f);
                if (ROUND_OUT) { v.x = f2tf32f(v.x); v.y = f2tf32f(v.y); }
                *(float2*)&outb[(size_t)m2 * HWc + nn] = v;
            }
        }
    } else {
        // ---- fused 1x1 head: per-CTA reduction over M ----
        const int NP = WROWS * 8;          // partials per output pixel
        float* red = sm;                   // reuse pipeline smem: 128*(NP+1) floats
        __syncthreads();                   // all compute done before overwrite

        float sc[TI], bi[TI], sc2[TI], bi2[TI], hwm[TI], hwm2[TI];
        #pragma unroll
        for (int ti = 0; ti < TI; ti++) {
            int m  = (mb0 + ti) * 16 + gid;
            int m2 = m + 8;
            sc[ti]  = gamma[m ] * BNSCALE; bi[ti]  = beta[m ]; hwm[ti]  = hw[m ];
            sc2[ti] = gamma[m2] * BNSCALE; bi2[ti] = beta[m2]; hwm2[ti] = hw[m2];
        }
        #pragma unroll
        for (int tj = 0; tj < TJ; tj++) {
            #pragma unroll
            for (int e = 0; e < 2; e++) {
                int nloc = nwb + tj * 8 + tig * 2 + e;
                float s = 0.f;
                #pragma unroll
                for (int ti = 0; ti < TI; ti++) {
                    float v1 = fmaxf(acc[ti][tj][0 + e] * sc[ti]  + bi[ti],  0.f);
                    float v2 = fmaxf(acc[ti][tj][2 + e] * sc2[ti] + bi2[ti], 0.f);
                    s += hwm[ti] * v1 + hwm2[ti] * v2;
                }
                red[nloc * (NP + 1) + wrow * 8 + gid] = s;
            }
        }
        __syncthreads();
        if (t < 128) {
            float s = hb[0];
            #pragma unroll
            for (int p = 0; p < NP; p++) s += red[t * (NP + 1) + p];
            float sg = 1.f / (1.f + expf(-s));
            if (HEAD == 1) out[(size_t)b * 2 * HWc + HWc + n0 + t] = sg;
            else           out[(size_t)b * HWc + n0 + t] = RMINf + sg * (RMAXf - RMINf);
        }
    }
}

// ================= peak extraction + top-k =================
__global__ void topk_kernel(const float* __restrict__ outbuf,
                            float* __restrict__ peaks,
                            float* __restrict__ centers)
{
    int b = blockIdx.x;
    const float* heat = outbuf + (size_t)b * 2 * HWc + HWc;
    float* pk = peaks + (size_t)b * HWc;
    int t = threadIdx.x;

    for (int p = t; p < HWc; p += 1024) {
        int y = p >> 7, x = p & 127;
        float v = heat[p];
        bool ismax = true;
        #pragma unroll
        for (int dy = -1; dy <= 1; dy++)
            #pragma unroll
            for (int dx = -1; dx <= 1; dx++) {
                if (dy == 0 && dx == 0) continue;
                int yy = y + dy, xx = x + dx;
                if ((unsigned)yy < Hh && (unsigned)xx < Ww)
                    if (heat[yy * Ww + xx] > v) ismax = false;
            }
        pk[p] = ismax ? v : 0.f;
    }
    __syncthreads();

    __shared__ float sv[1024];
    __shared__ int   si[1024];

    for (int k = 0; k < Kk; k++) {
        float bv = -2.f; int bi = 0x7fffffff;
        for (int p = t; p < HWc; p += 1024) {
            float v = pk[p];
            if (v > bv) { bv = v; bi = p; }
        }
        sv[t] = bv; si[t] = bi;
        __syncthreads();
        for (int s = 512; s > 0; s >>= 1) {
            if (t < s) {
                if (sv[t+s] > sv[t] || (sv[t+s] == sv[t] && si[t+s] < si[t])) {
                    sv[t] = sv[t+s]; si[t] = si[t+s];
                }
            }
            __syncthreads();
        }
        if (t == 0) {
            float v = sv[0]; int idx = si[0];
            pk[idx] = -1.f;
            float valid = (v >= THRf) ? 1.f : 0.f;
            float row = (float)(idx >> 7);
            float col = (float)(idx & 127);
            float ny = 2.f * row / (float)(Hh - 1) - 1.f;
            float nx = 2.f * col / (float)(Ww - 1) - 1.f;
            centers[(b * Kk + k) * 3 + 0] = nx * valid;
            centers[(b * Kk + k) * 3 + 1] = ny * valid;
            centers[(b * Kk + k) * 3 + 2] = valid;
        }
        __syncthreads();
    }
}

// ================= bilinear + MLP + per-peak params =================
__global__ void mlp_kernel(const float* __restrict__ x,
                           const float* __restrict__ rmap,
                           const float* __restrict__ centers,
                           const float* __restrict__ w1, const float* __restrict__ b1,
                           const float* __restrict__ w2, const float* __restrict__ b2,
                           const float* __restrict__ log_alpha,
                           float* __restrict__ params)
{
    int bk = blockIdx.x;
    int b  = bk / Kk;
    int t  = threadIdx.x;

    float cx = centers[bk*3+0], cy = centers[bk*3+1], valid = centers[bk*3+2];

    float px = fminf(fmaxf((cx + 1.f) * 0.5f * (float)(Ww - 1), 0.f), (float)(Ww - 1));
    float py = fminf(fmaxf((cy + 1.f) * 0.5f * (float)(Hh - 1), 0.f), (float)(Hh - 1));
    int x0 = (int)floorf(px); int x1 = min(x0 + 1, Ww - 1);
    int y0 = (int)floorf(py); int y1 = min(y0 + 1, Hh - 1);
    float wx = px - (float)x0, wy = py - (float)y0;

    __shared__ float feat[Cc];
    const float* xb = x + (size_t)b * Cc * HWc;
    for (int c = t; c < Cc; c += 128) {
        const float* f = xb + (size_t)c * HWc;
        float v00 = f[y0*Ww + x0], v01 = f[y0*Ww + x1];
        float v10 = f[y1*Ww + x0], v11 = f[y1*Ww + x1];
        feat[c] = (1.f - wy) * ((1.f - wx)*v00 + wx*v01)
                +        wy  * ((1.f - wx)*v10 + wx*v11);
    }
    __syncthreads();

    float h = b1[t];
    #pragma unroll 8
    for (int c = 0; c < Cc; c++) h += feat[c] * w1[c * 128 + t];
    h = fmaxf(h, 0.f);

    __shared__ float red[4][128];
    #pragma unroll
    for (int q = 0; q < 4; q++) red[q][t] = h * w2[t * 4 + q];
    __syncthreads();
    for (int s = 64; s > 0; s >>= 1) {
        if (t < s)
            #pragma unroll
            for (int q = 0; q < 4; q++) red[q][t] += red[q][t + s];
        __syncthreads();
    }

    if (t == 0) {
        float p0 = red[0][0] + b2[0];
        float p1 = red[1][0] + b2[1];
        float p2 = red[2][0] + b2[2];
        float p3 = red[3][0] + b2[3];
        float dsx   = tanhf(p0) * DMAXf;
        float dsy   = tanhf(p1) * DMAXf;
        float theta = tanhf(p2) * PIf;
        float wgt   = 1.f / (1.f + expf(-p3));

        const float* rm = rmap + (size_t)b * HWc;
        float rk = (1.f - wy) * ((1.f - wx)*rm[y0*Ww + x0] + wx*rm[y0*Ww + x1])
                 +        wy  * ((1.f - wx)*rm[y1*Ww + x0] + wx*rm[y1*Ww + x1]);

        float la = log_alpha[0];
        float alpha = (la > 20.f) ? la : log1pf(expf(la));
        float sx = fminf(fmaxf(alpha * rk + dsx, SMINf), SMAXf);
        float sy = fminf(fmaxf(alpha * rk * BETAf + dsy, SMINf), SMAXf);

        float* pp = params + bk * 8;
        pp[0] = cx; pp[1] = cy;
        pp[2] = cosf(theta); pp[3] = sinf(theta);
        pp[4] = 1.f / (2.f * sx * sx + 1e-6f);
        pp[5] = 1.f / (2.f * sy * sy + 1e-6f);
        pp[6] = wgt * valid;
        pp[7] = valid;
    }
}

// ================= Gaussian mixture -> attn =================
__global__ void gauss_kernel(const float* __restrict__ params,
                             float* __restrict__ out)
{
    int idx = blockIdx.x * 256 + threadIdx.x;
    int b = idx >> 14;
    int p = idx & (HWc - 1);

    __shared__ float sp[Kk * 8];
    if (threadIdx.x < Kk * 8) sp[threadIdx.x] = params[b * Kk * 8 + threadIdx.x];
    __syncthreads();

    float gx = 2.f * (float)(p & 127) / (float)(Ww - 1) - 1.f;
    float gy = 2.f * (float)(p >> 7)  / (float)(Hh - 1) - 1.f;

    float wsum = 0.f;
    #pragma unroll
    for (int k = 0; k < Kk; k++) wsum += sp[k*8 + 6];
    wsum = fmaxf(wsum, 1e-6f);

    float mix = 0.f;
    #pragma unroll
    for (int k = 0; k < Kk; k++) {
        float mw = sp[k*8 + 6];
        float dx = gx - sp[k*8 + 0];
        float dy = gy - sp[k*8 + 1];
        float ct = sp[k*8 + 2], st = sp[k*8 + 3];
        float xr =  ct * dx + st * dy;
        float yr = -st * dx + ct * dy;
        float G = expf(-(xr * xr * sp[k*8 + 4] + yr * yr * sp[k*8 + 5]));
        mix += G * (mw / wsum) * sp[k*8 + 7];
    }
    float attn = 1.f / (1.f + expf(-(4.f * mix - 2.f)));
    out[(size_t)b * 2 * HWc + p] = attn;
}

// ================= launch =================
#define AW_128 (128 * 16)
#define AW_64  (64 * 16)
#define SM_128 (NSTAGE * (AW_128 + B_W) * 4)   // 67584
#define SM_64  (NSTAGE * (AW_64  + B_W) * 4)   // 51200

extern "C" void kernel_launch(void* const* d_in, const int* in_sizes, int n_in,
                              void* d_out, int out_size)
{
    const float* x        = (const float*)d_in[0];
    const float* hm_dw    = (const float*)d_in[1];
    const float* hm_pw1   = (const float*)d_in[2];
    const float* hm_g1    = (const float*)d_in[3];
    const float* hm_b1    = (const float*)d_in[4];
    const float* hm_c3    = (const float*)d_in[5];
    const float* hm_g2    = (const float*)d_in[6];
    const float* hm_b2    = (const float*)d_in[7];
    const float* hm_out_w = (const float*)d_in[8];
    const float* hm_out_b = (const float*)d_in[9];
    const float* r_dw     = (const float*)d_in[10];
    const float* r_pw1    = (const float*)d_in[11];
    const float* r_g      = (const float*)d_in[12];
    const float* r_b      = (const float*)d_in[13];
    const float* r_out_w  = (const float*)d_in[14];
    const float* r_out_b  = (const float*)d_in[15];
    const float* log_alpha= (const float*)d_in[16];
    const float* mlp_w1   = (const float*)d_in[17];
    const float* mlp_b1   = (const float*)d_in[18];
    const float* mlp_w2   = (const float*)d_in[19];
    const float* mlp_b2   = (const float*)d_in[20];
    float* out = (float*)d_out;

    float *t, *t2, *h1, *rmap, *peaks, *centers, *params;
    float *w1c, *w3c, *wrc;
    cudaGetSymbolAddress((void**)&t,       g_t);
    cudaGetSymbolAddress((void**)&t2,      g_t2);
    cudaGetSymbolAddress((void**)&h1,      g_h1);
    cudaGetSymbolAddress((void**)&rmap,    g_rmap);
    cudaGetSymbolAddress((void**)&peaks,   g_peaks);
    cudaGetSymbolAddress((void**)&centers, g_centers);
    cudaGetSymbolAddress((void**)&params,  g_params);
    cudaGetSymbolAddress((void**)&w1c,     g_w1c);
    cudaGetSymbolAddress((void**)&w3c,     g_w3c);
    cudaGetSymbolAddress((void**)&wrc,     g_wrc);

    cudaFuncSetAttribute((const void*)mma_gemm<0,4,4,2,true ,AW_128,0>,
                         cudaFuncAttributeMaxDynamicSharedMemorySize, SM_128);
    cudaFuncSetAttribute((const void*)mma_gemm<1,4,4,2,false,AW_128,1>,
                         cudaFuncAttributeMaxDynamicSharedMemorySize, SM_128);
    cudaFuncSetAttribute((const void*)mma_gemm<0,4,2,1,false,AW_64 ,2>,
                         cudaFuncAttributeMaxDynamicSharedMemorySize, SM_64);

    dim3 gGrid(HWc / 128, 1, Bn);

    // weight swizzle + tf32 rounding
    swizzleA<<<(MIDc * Cc        + 255) / 256, 256>>>(hm_pw1, w1c, MIDc,  Cc,       8, 0);
    swizzleA<<<(MIDc * MIDc * 9  + 255) / 256, 256>>>(hm_c3,  w3c, MIDc,  MIDc * 9, 8, 1);
    swizzleA<<<(RMIDc * Cc       + 255) / 256, 256>>>(r_pw1,  wrc, RMIDc, Cc,       4, 0);

    // fused depthwise for both branches
    dw3x3_dual<<<Bn * Cc, 256>>>(x, hm_dw, r_dw, t, t2);

    // heat branch: pw1 -> h1, then c3 + fused heat head -> out (heat channel)
    mma_gemm<0,4,4,2,true ,AW_128,0><<<gGrid, 256, SM_128>>>(
        t,  w1c, hm_g1, hm_b1, (const float*)0, (const float*)0, h1, MIDc, Cc, Cc);
    mma_gemm<1,4,4,2,false,AW_128,1><<<gGrid, 256, SM_128>>>(
        h1, w3c, hm_g2, hm_b2, hm_out_w, hm_out_b, out, MIDc, MIDc * 9, MIDc);

    // radius branch: pw1 + fused radius head -> rmap
    mma_gemm<0,4,2,1,false,AW_64,2><<<gGrid, 256, SM_64>>>(
        t2, wrc, r_g, r_b, r_out_w, r_out_b, rmap, RMIDc, Cc, Cc);

    // peaks -> centers
    topk_kernel<<<Bn, 1024>>>(out, peaks, centers);

    // bilinear sample + MLP -> per-peak gaussian params
    mlp_kernel<<<Bn * Kk, 128>>>(x, rmap, centers, mlp_w1, mlp_b1, mlp_w2, mlp_b2,
                                 log_alpha, params);

    // gaussian mixture -> attn channel
    gauss_kernel<<<Bn * HWc / 256, 256>>>(params, out);
}

// round 17
// speedup vs baseline: 1.0030x; 1.0030x over previous
#include <cuda_runtime.h>
#include <math.h>
#include <stdint.h>

// ---------------- problem constants ----------------
#define Bn   8
#define Cc   256
#define Hh   128
#define Ww   128
#define HWc  16384
#define MIDc 128
#define RMIDc 64
#define Kk   5
#define THRf   0.1f
#define SMINf  0.05f
#define SMAXf  0.45f
#define BETAf  1.5f
#define DMAXf  0.08f
#define RMINf  0.03f
#define RMAXf  0.4f
#define PIf    3.14159265358979323846f
#define BNSCALE 0.99999500003749971f

// ---------------- scratch ----------------
__device__ __align__(16) float g_t  [(size_t)Bn * Cc   * HWc];
__device__ __align__(16) float g_t2 [(size_t)Bn * Cc   * HWc];
__device__ __align__(16) float g_h1 [(size_t)Bn * MIDc * HWc];
__device__ __align__(16) float g_rmap[Bn * HWc];
__device__ __align__(16) float g_peaks[Bn * HWc];
__device__ __align__(16) float g_centers[Bn * Kk * 3];
__device__ __align__(16) float g_params [Bn * Kk * 8];
// fragment-swizzled, tf32-rounded weights
__device__ __align__(16) float g_w1c[MIDc * Cc];
__device__ __align__(16) float g_w3c[MIDc * MIDc * 9];
__device__ __align__(16) float g_wrc[RMIDc * Cc];

__device__ __forceinline__ uint32_t f2tf32(float x) {
    uint32_t r;
    asm("cvt.rna.tf32.f32 %0, %1;" : "=r"(r) : "f"(x));
    return r;
}
__device__ __forceinline__ float f2tf32f(float x) { return __uint_as_float(f2tf32(x)); }

__device__ __forceinline__ void mma_tf32(float c[4],
                                         uint32_t a0, uint32_t a1, uint32_t a2, uint32_t a3,
                                         uint32_t b0, uint32_t b1) {
    asm volatile(
        "mma.sync.aligned.m16n8k8.row.col.f32.tf32.tf32.f32 "
        "{%0,%1,%2,%3}, {%4,%5,%6,%7}, {%8,%9}, {%0,%1,%2,%3};\n"
        : "+f"(c[0]), "+f"(c[1]), "+f"(c[2]), "+f"(c[3])
        : "r"(a0), "r"(a1), "r"(a2), "r"(a3), "r"(b0), "r"(b1));
}

__device__ __forceinline__ void cp16(uint32_t dst, const void* src) {
    asm volatile("cp.async.cg.shared.global [%0], [%1], 16;\n" :: "r"(dst), "l"(src));
}
__device__ __forceinline__ void cp4(uint32_t dst, const void* src, int sz) {
    asm volatile("cp.async.ca.shared.global [%0], [%1], 4, %2;\n"
                 :: "r"(dst), "l"(src), "r"(sz));
}
#define CP_COMMIT() asm volatile("cp.async.commit_group;\n" ::: "memory")
template<int N> __device__ __forceinline__ void cp_wait() {
    asm volatile("cp.async.wait_group %0;\n" :: "n"(N) : "memory");
}

// ================= weight swizzle: fragment-ready layout, tf32-rounded =================
__global__ void swizzleA(const float* __restrict__ src, float* __restrict__ dst,
                         int M, int K, int MB, int conv)
{
    int i = blockIdx.x * 256 + threadIdx.x;
    if (i >= M * K) return;
    int q    = i & 3;
    int lane = (i >> 2) & 31;
    int kh   = (i >> 7) & 1;
    int rest = i >> 8;
    int mb   = rest % MB;
    int kt   = rest / MB;
    int m  = mb * 16 + (lane >> 2) + (q & 1) * 8;
    int k  = kt * 16 + kh * 8 + (lane & 3) + ((q >> 1) << 2);
    int sc = conv ? ((k & 127) * 9 + (k >> 7)) : k;
    dst[i] = f2tf32f(src[(size_t)m * K + sc]);
}

// ================= fused dual depthwise 3x3 (pad=1): register-sliding float4 =====
// One CTA per (b,c) plane; 8 warps x 16 rows; lane owns 4 cols (float4).
struct DwRow { float4 m, l, r; };

__global__ __launch_bounds__(256)
void dw3x3_dual(const float* __restrict__ in,
                const float* __restrict__ w1,
                const float* __restrict__ w2,
                float* __restrict__ out1,
                float* __restrict__ out2)
{
    int zc = blockIdx.x;                // b*C + c
    int c  = zc & (Cc - 1);
    const float4* inp = (const float4*)(in   + (size_t)zc * HWc);
    float4*       o1  = (float4*)      (out1 + (size_t)zc * HWc);
    float4*       o2  = (float4*)      (out2 + (size_t)zc * HWc);

    int lane = threadIdx.x & 31, w = threadIdx.x >> 5;
    int y0 = w * 16;

    float wa[9], wb[9];
    #pragma unroll
    for (int i = 0; i < 9; i++) { wa[i] = w1[c*9+i]; wb[i] = w2[c*9+i]; }

    auto loadrow = [&](int y) -> DwRow {
        DwRow R;
        if ((unsigned)y < (unsigned)Hh) R.m = inp[y * 32 + lane];
        else R.m = make_float4(0.f, 0.f, 0.f, 0.f);
        float lx = __shfl_up_sync(0xffffffffu, R.m.w, 1);
        float rx = __shfl_down_sync(0xffffffffu, R.m.x, 1);
        if (lane == 0)  lx = 0.f;
        if (lane == 31) rx = 0.f;
        R.l = make_float4(lx, R.m.x, R.m.y, R.m.z);
        R.r = make_float4(R.m.y, R.m.z, R.m.w, rx);
        return R;
    };

    DwRow rp = loadrow(y0 - 1);
    DwRow rc = loadrow(y0);

    #pragma unroll 4
    for (int y = y0; y < y0 + 16; y++) {
        DwRow rn = loadrow(y + 1);

        float4 s1, s2;
        #define CONV_C(dst, W, CMP) \
            dst.CMP = W[0]*rp.l.CMP + W[1]*rp.m.CMP + W[2]*rp.r.CMP \
                    + W[3]*rc.l.CMP + W[4]*rc.m.CMP + W[5]*rc.r.CMP \
                    + W[6]*rn.l.CMP + W[7]*rn.m.CMP + W[8]*rn.r.CMP;
        CONV_C(s1, wa, x) CONV_C(s1, wa, y) CONV_C(s1, wa, z) CONV_C(s1, wa, w)
        CONV_C(s2, wb, x) CONV_C(s2, wb, y) CONV_C(s2, wb, z) CONV_C(s2, wb, w)
        #undef CONV_C

        float4 t1 = make_float4(f2tf32f(s1.x), f2tf32f(s1.y), f2tf32f(s1.z), f2tf32f(s1.w));
        float4 t2 = make_float4(f2tf32f(s2.x), f2tf32f(s2.y), f2tf32f(s2.z), f2tf32f(s2.w));
        o1[y * 32 + lane] = t1;
        o2[y * 32 + lane] = t2;

        rp = rc; rc = rn;
    }
}

// ================= TF32 tensor-core GEMM, 4-stage cp.async, fragment-swizzled A =====
// HEAD 0: write full (M, HW) matrix (BN+ReLU, opt tf32-round)
// HEAD 1: fused heat head   -> out[b*2HW + HW + n] = sigmoid(sum_m hw[m]*relu(bn))+...
// HEAD 2: fused radius head -> out[b*HW + n] = RMIN + sigmoid(.)*(RMAX-RMIN)
#define BST 136
#define B_W (16 * BST)
#define NSTAGE 4

template<int MODE, int TI, int TJ, int WROWS, bool ROUND_OUT, int AW, int HEAD>
__global__ __launch_bounds__(256, 2)
void mma_gemm(const float* __restrict__ in,
              const float* __restrict__ wA,
              const float* __restrict__ gamma,
              const float* __restrict__ beta,
              const float* __restrict__ hw,
              const float* __restrict__ hb,
              float* __restrict__ out,
              int M, int Kdim, int Cin)
{
    extern __shared__ float sm[];
    float* smA = sm;
    float* smB = sm + NSTAGE * AW;
    uint32_t smA_addr = (uint32_t)__cvta_generic_to_shared(smA);
    uint32_t smB_addr = (uint32_t)__cvta_generic_to_shared(smB);

    const int WCOLS = 8 / WROWS;

    int b  = blockIdx.z;
    int n0 = blockIdx.x * 128;
    int y  = blockIdx.x;                  // MODE 1: image row
    const float* inb = in + (size_t)b * Cin * HWc;

    int t = threadIdx.x;
    int lane = t & 31, w = t >> 5;
    int wrow = w / WCOLS, wcol = w % WCOLS;
    int mb0 = wrow * TI;
    int nwb = wcol * (TJ * 8);
    int gid = lane >> 2, tig = lane & 3;

    int nl = t & 127, kb = t >> 7;        // MODE1 B
    int kB = t >> 5, ngB = t & 31;        // MODE0 B

    float acc[TI][TJ][4];
    #pragma unroll
    for (int i = 0; i < TI; i++)
        #pragma unroll
        for (int j = 0; j < TJ; j++)
            #pragma unroll
            for (int q = 0; q < 4; q++) acc[i][j][q] = 0.f;

    int KT = Kdim / 16;

    auto load_stage = [&](int st, int kt) {
        #pragma unroll
        for (int c = 0; c < AW / 4 / 256; c++) {
            int ch = t + c * 256;
            cp16(smA_addr + (uint32_t)(st * AW + ch * 4) * 4u, wA + (size_t)kt * AW + ch * 4);
        }
        if (MODE == 0) {
            int k0 = kt * 16;
            #pragma unroll
            for (int jj = 0; jj < 2; jj++) {
                int k = kB + jj * 8;
                cp16(smB_addr + (uint32_t)(st * B_W + k * BST + ngB * 4) * 4u,
                     inb + (size_t)(k0 + k) * HWc + n0 + ngB * 4);
            }
        } else {
            int tp  = kt >> 3;
            int dy  = tp / 3;
            int dx  = tp - dy * 3;
            int ci0 = (kt & 7) * 16;
            int yy  = y + dy - 1;
            int xx  = nl + dx - 1;
            bool ok = ((unsigned)yy < (unsigned)Hh) && ((unsigned)xx < (unsigned)Ww);
            const float* src = inb + (size_t)(ci0 + kb * 8) * HWc
                             + (ok ? (yy * Ww + xx) : 0);
            uint32_t dst = smB_addr + (uint32_t)(st * B_W + kb * 8 * BST + nl) * 4u;
            int sz = ok ? 4 : 0;
            #pragma unroll
            for (int j = 0; j < 8; j++)
                cp4(dst + (uint32_t)(j * BST) * 4u, src + (size_t)j * HWc, sz);
        }
    };

    auto compute = [&](int st) {
        const uint4*    A  = (const uint4*)(smA + st * AW);
        const uint32_t* Bq = (const uint32_t*)smB + st * B_W;
        #pragma unroll
        for (int kh = 0; kh < 2; kh++) {
            uint4 a[TI];
            #pragma unroll
            for (int ti = 0; ti < TI; ti++)
                a[ti] = A[((mb0 + ti) * 2 + kh) * 32 + lane];
            uint32_t bf[TJ][2];
            #pragma unroll
            for (int tj = 0; tj < TJ; tj++) {
                int nn = nwb + tj * 8 + gid;
                bf[tj][0] = Bq[(kh * 8 + tig    ) * BST + nn];
                bf[tj][1] = Bq[(kh * 8 + tig + 4) * BST + nn];
            }
            #pragma unroll
            for (int ti = 0; ti < TI; ti++)
                #pragma unroll
                for (int tj = 0; tj < TJ; tj++)
                    mma_tf32(acc[ti][tj], a[ti].x, a[ti].y, a[ti].z, a[ti].w,
                             bf[tj][0], bf[tj][1]);
        }
    };

    load_stage(0, 0); CP_COMMIT();
    load_stage(1, 1); CP_COMMIT();
    load_stage(2, 2); CP_COMMIT();

    for (int kt = 0; kt < KT; kt++) {
        cp_wait<2>();
        __syncthreads();
        if (kt + 3 < KT) load_stage((kt + 3) & 3, kt + 3);
        CP_COMMIT();
        compute(kt & 3);
    }

    if (HEAD == 0) {
        // ---- epilogue: BN + ReLU, write fp32 matrix ----
        float* outb = out + (size_t)b * M * HWc;
        #pragma unroll
        for (int ti = 0; ti < TI; ti++) {
            int m  = (mb0 + ti) * 16 + gid;
            int m2 = m + 8;
            float sc  = gamma[m ] * BNSCALE, bi  = beta[m ];
            float sc2 = gamma[m2] * BNSCALE, bi2 = beta[m2];
            #pragma unroll
            for (int tj = 0; tj < TJ; tj++) {
                int nn = n0 + nwb + tj * 8 + tig * 2;
                float2 v;
                v.x = fmaxf(acc[ti][tj][0] * sc + bi, 0.f);
                v.y = fmaxf(acc[ti][tj][1] * sc + bi, 0.f);
                if (ROUND_OUT) { v.x = f2tf32f(v.x); v.y = f2tf32f(v.y); }
                *(float2*)&outb[(size_t)m * HWc + nn] = v;
                v.x = fmaxf(acc[ti][tj][2] * sc2 + bi2, 0.f);
                v.y = fmaxf(acc[ti][tj][3] * sc2 + bi2, 0.f);
                if (ROUND_OUT) { v.x = f2tf32f(v.x); v.y = f2tf32f(v.y); }
                *(float2*)&outb[(size_t)m2 * HWc + nn] = v;
            }
        }
    } else {
        // ---- fused 1x1 head: per-CTA reduction over M ----
        const int NP = WROWS * 8;          // partials per output pixel
        float* red = sm;                   // reuse pipeline smem: 128*(NP+1) floats
        __syncthreads();                   // all compute done before overwrite

        float sc[TI], bi[TI], sc2[TI], bi2[TI], hwm[TI], hwm2[TI];
        #pragma unroll
        for (int ti = 0; ti < TI; ti++) {
            int m  = (mb0 + ti) * 16 + gid;
            int m2 = m + 8;
            sc[ti]  = gamma[m ] * BNSCALE; bi[ti]  = beta[m ]; hwm[ti]  = hw[m ];
            sc2[ti] = gamma[m2] * BNSCALE; bi2[ti] = beta[m2]; hwm2[ti] = hw[m2];
        }
        #pragma unroll
        for (int tj = 0; tj < TJ; tj++) {
            #pragma unroll
            for (int e = 0; e < 2; e++) {
                int nloc = nwb + tj * 8 + tig * 2 + e;
                float s = 0.f;
                #pragma unroll
                for (int ti = 0; ti < TI; ti++) {
                    float v1 = fmaxf(acc[ti][tj][0 + e] * sc[ti]  + bi[ti],  0.f);
                    float v2 = fmaxf(acc[ti][tj][2 + e] * sc2[ti] + bi2[ti], 0.f);
                    s += hwm[ti] * v1 + hwm2[ti] * v2;
                }
                red[nloc * (NP + 1) + wrow * 8 + gid] = s;
            }
        }
        __syncthreads();
        if (t < 128) {
            float s = hb[0];
            #pragma unroll
            for (int p = 0; p < NP; p++) s += red[t * (NP + 1) + p];
            float sg = 1.f / (1.f + expf(-s));
            if (HEAD == 1) out[(size_t)b * 2 * HWc + HWc + n0 + t] = sg;
            else           out[(size_t)b * HWc + n0 + t] = RMINf + sg * (RMAXf - RMINf);
        }
    }
}

// ================= peak extraction + top-k =================
__global__ void topk_kernel(const float* __restrict__ outbuf,
                            float* __restrict__ peaks,
                            float* __restrict__ centers)
{
    int b = blockIdx.x;
    const float* heat = outbuf + (size_t)b * 2 * HWc + HWc;
    float* pk = peaks + (size_t)b * HWc;
    int t = threadIdx.x;

    for (int p = t; p < HWc; p += 1024) {
        int y = p >> 7, x = p & 127;
        float v = heat[p];
        bool ismax = true;
        #pragma unroll
        for (int dy = -1; dy <= 1; dy++)
            #pragma unroll
            for (int dx = -1; dx <= 1; dx++) {
                if (dy == 0 && dx == 0) continue;
                int yy = y + dy, xx = x + dx;
                if ((unsigned)yy < Hh && (unsigned)xx < Ww)
                    if (heat[yy * Ww + xx] > v) ismax = false;
            }
        pk[p] = ismax ? v : 0.f;
    }
    __syncthreads();

    __shared__ float sv[1024];
    __shared__ int   si[1024];

    for (int k = 0; k < Kk; k++) {
        float bv = -2.f; int bi = 0x7fffffff;
        for (int p = t; p < HWc; p += 1024) {
            float v = pk[p];
            if (v > bv) { bv = v; bi = p; }
        }
        sv[t] = bv; si[t] = bi;
        __syncthreads();
        for (int s = 512; s > 0; s >>= 1) {
            if (t < s) {
                if (sv[t+s] > sv[t] || (sv[t+s] == sv[t] && si[t+s] < si[t])) {
                    sv[t] = sv[t+s]; si[t] = si[t+s];
                }
            }
            __syncthreads();
        }
        if (t == 0) {
            float v = sv[0]; int idx = si[0];
            pk[idx] = -1.f;
            float valid = (v >= THRf) ? 1.f : 0.f;
            float row = (float)(idx >> 7);
            float col = (float)(idx & 127);
            float ny = 2.f * row / (float)(Hh - 1) - 1.f;
            float nx = 2.f * col / (float)(Ww - 1) - 1.f;
            centers[(b * Kk + k) * 3 + 0] = nx * valid;
            centers[(b * Kk + k) * 3 + 1] = ny * valid;
            centers[(b * Kk + k) * 3 + 2] = valid;
        }
        __syncthreads();
    }
}

// ================= bilinear + MLP + per-peak params =================
__global__ void mlp_kernel(const float* __restrict__ x,
                           const float* __restrict__ rmap,
                           const float* __restrict__ centers,
                           const float* __restrict__ w1, const float* __restrict__ b1,
                           const float* __restrict__ w2, const float* __restrict__ b2,
                           const float* __restrict__ log_alpha,
                           float* __restrict__ params)
{
    int bk = blockIdx.x;
    int b  = bk / Kk;
    int t  = threadIdx.x;

    float cx = centers[bk*3+0], cy = centers[bk*3+1], valid = centers[bk*3+2];

    float px = fminf(fmaxf((cx + 1.f) * 0.5f * (float)(Ww - 1), 0.f), (float)(Ww - 1));
    float py = fminf(fmaxf((cy + 1.f) * 0.5f * (float)(Hh - 1), 0.f), (float)(Hh - 1));
    int x0 = (int)floorf(px); int x1 = min(x0 + 1, Ww - 1);
    int y0 = (int)floorf(py); int y1 = min(y0 + 1, Hh - 1);
    float wx = px - (float)x0, wy = py - (float)y0;

    __shared__ float feat[Cc];
    const float* xb = x + (size_t)b * Cc * HWc;
    for (int c = t; c < Cc; c += 128) {
        const float* f = xb + (size_t)c * HWc;
        float v00 = f[y0*Ww + x0], v01 = f[y0*Ww + x1];
        float v10 = f[y1*Ww + x0], v11 = f[y1*Ww + x1];
        feat[c] = (1.f - wy) * ((1.f - wx)*v00 + wx*v01)
                +        wy  * ((1.f - wx)*v10 + wx*v11);
    }
    __syncthreads();

    float h = b1[t];
    #pragma unroll 8
    for (int c = 0; c < Cc; c++) h += feat[c] * w1[c * 128 + t];
    h = fmaxf(h, 0.f);

    __shared__ float red[4][128];
    #pragma unroll
    for (int q = 0; q < 4; q++) red[q][t] = h * w2[t * 4 + q];
    __syncthreads();
    for (int s = 64; s > 0; s >>= 1) {
        if (t < s)
            #pragma unroll
            for (int q = 0; q < 4; q++) red[q][t] += red[q][t + s];
        __syncthreads();
    }

    if (t == 0) {
        float p0 = red[0][0] + b2[0];
        float p1 = red[1][0] + b2[1];
        float p2 = red[2][0] + b2[2];
        float p3 = red[3][0] + b2[3];
        float dsx   = tanhf(p0) * DMAXf;
        float dsy   = tanhf(p1) * DMAXf;
        float theta = tanhf(p2) * PIf;
        float wgt   = 1.f / (1.f + expf(-p3));

        const float* rm = rmap + (size_t)b * HWc;
        float rk = (1.f - wy) * ((1.f - wx)*rm[y0*Ww + x0] + wx*rm[y0*Ww + x1])
                 +        wy  * ((1.f - wx)*rm[y1*Ww + x0] + wx*rm[y1*Ww + x1]);

        float la = log_alpha[0];
        float alpha = (la > 20.f) ? la : log1pf(expf(la));
        float sx = fminf(fmaxf(alpha * rk + dsx, SMINf), SMAXf);
        float sy = fminf(fmaxf(alpha * rk * BETAf + dsy, SMINf), SMAXf);

        float* pp = params + bk * 8;
        pp[0] = cx; pp[1] = cy;
        pp[2] = cosf(theta); pp[3] = sinf(theta);
        pp[4] = 1.f / (2.f * sx * sx + 1e-6f);
        pp[5] = 1.f / (2.f * sy * sy + 1e-6f);
        pp[6] = wgt * valid;
        pp[7] = valid;
    }
}

// ================= Gaussian mixture -> attn =================
__global__ void gauss_kernel(const float* __restrict__ params,
                             float* __restrict__ out)
{
    int idx = blockIdx.x * 256 + threadIdx.x;
    int b = idx >> 14;
    int p = idx & (HWc - 1);

    __shared__ float sp[Kk * 8];
    if (threadIdx.x < Kk * 8) sp[threadIdx.x] = params[b * Kk * 8 + threadIdx.x];
    __syncthreads();

    float gx = 2.f * (float)(p & 127) / (float)(Ww - 1) - 1.f;
    float gy = 2.f * (float)(p >> 7)  / (float)(Hh - 1) - 1.f;

    float wsum = 0.f;
    #pragma unroll
    for (int k = 0; k < Kk; k++) wsum += sp[k*8 + 6];
    wsum = fmaxf(wsum, 1e-6f);

    float mix = 0.f;
    #pragma unroll
    for (int k = 0; k < Kk; k++) {
        float mw = sp[k*8 + 6];
        float dx = gx - sp[k*8 + 0];
        float dy = gy - sp[k*8 + 1];
        float ct = sp[k*8 + 2], st = sp[k*8 + 3];
        float xr =  ct * dx + st * dy;
        float yr = -st * dx + ct * dy;
        float G = expf(-(xr * xr * sp[k*8 + 4] + yr * yr * sp[k*8 + 5]));
        mix += G * (mw / wsum) * sp[k*8 + 7];
    }
    float attn = 1.f / (1.f + expf(-(4.f * mix - 2.f)));
    out[(size_t)b * 2 * HWc + p] = attn;
}

// ================= launch =================
#define AW_128 (128 * 16)
#define AW_64  (64 * 16)
#define SM_128 (NSTAGE * (AW_128 + B_W) * 4)   // 67584
#define SM_64  (NSTAGE * (AW_64  + B_W) * 4)   // 51200

extern "C" void kernel_launch(void* const* d_in, const int* in_sizes, int n_in,
                              void* d_out, int out_size)
{
    const float* x        = (const float*)d_in[0];
    const float* hm_dw    = (const float*)d_in[1];
    const float* hm_pw1   = (const float*)d_in[2];
    const float* hm_g1    = (const float*)d_in[3];
    const float* hm_b1    = (const float*)d_in[4];
    const float* hm_c3    = (const float*)d_in[5];
    const float* hm_g2    = (const float*)d_in[6];
    const float* hm_b2    = (const float*)d_in[7];
    const float* hm_out_w = (const float*)d_in[8];
    const float* hm_out_b = (const float*)d_in[9];
    const float* r_dw     = (const float*)d_in[10];
    const float* r_pw1    = (const float*)d_in[11];
    const float* r_g      = (const float*)d_in[12];
    const float* r_b      = (const float*)d_in[13];
    const float* r_out_w  = (const float*)d_in[14];
    const float* r_out_b  = (const float*)d_in[15];
    const float* log_alpha= (const float*)d_in[16];
    const float* mlp_w1   = (const float*)d_in[17];
    const float* mlp_b1   = (const float*)d_in[18];
    const float* mlp_w2   = (const float*)d_in[19];
    const float* mlp_b2   = (const float*)d_in[20];
    float* out = (float*)d_out;

    float *t, *t2, *h1, *rmap, *peaks, *centers, *params;
    float *w1c, *w3c, *wrc;
    cudaGetSymbolAddress((void**)&t,       g_t);
    cudaGetSymbolAddress((void**)&t2,      g_t2);
    cudaGetSymbolAddress((void**)&h1,      g_h1);
    cudaGetSymbolAddress((void**)&rmap,    g_rmap);
    cudaGetSymbolAddress((void**)&peaks,   g_peaks);
    cudaGetSymbolAddress((void**)&centers, g_centers);
    cudaGetSymbolAddress((void**)&params,  g_params);
    cudaGetSymbolAddress((void**)&w1c,     g_w1c);
    cudaGetSymbolAddress((void**)&w3c,     g_w3c);
    cudaGetSymbolAddress((void**)&wrc,     g_wrc);

    cudaFuncSetAttribute((const void*)mma_gemm<0,4,4,2,true ,AW_128,0>,
                         cudaFuncAttributeMaxDynamicSharedMemorySize, SM_128);
    cudaFuncSetAttribute((const void*)mma_gemm<1,4,4,2,false,AW_128,1>,
                         cudaFuncAttributeMaxDynamicSharedMemorySize, SM_128);
    cudaFuncSetAttribute((const void*)mma_gemm<0,4,2,1,false,AW_64 ,2>,
                         cudaFuncAttributeMaxDynamicSharedMemorySize, SM_64);

    dim3 gGrid(HWc / 128, 1, Bn);

    // weight swizzle + tf32 rounding
    swizzleA<<<(MIDc * Cc        + 255) / 256, 256>>>(hm_pw1, w1c, MIDc,  Cc,       8, 0);
    swizzleA<<<(MIDc * MIDc * 9  + 255) / 256, 256>>>(hm_c3,  w3c, MIDc,  MIDc * 9, 8, 1);
    swizzleA<<<(RMIDc * Cc       + 255) / 256, 256>>>(r_pw1,  wrc, RMIDc, Cc,       4, 0);

    // fused depthwise for both branches
    dw3x3_dual<<<Bn * Cc, 256>>>(x, hm_dw, r_dw, t, t2);

    // heat branch: pw1 -> h1, then c3 + fused heat head -> out (heat channel)
    mma_gemm<0,4,4,2,true ,AW_128,0><<<gGrid, 256, SM_128>>>(
        t,  w1c, hm_g1, hm_b1, (const float*)0, (const float*)0, h1, MIDc, Cc, Cc);
    mma_gemm<1,4,4,2,false,AW_128,1><<<gGrid, 256, SM_128>>>(
        h1, w3c, hm_g2, hm_b2, hm_out_w, hm_out_b, out, MIDc, MIDc * 9, MIDc);

    // radius branch: pw1 + fused radius head -> rmap
    mma_gemm<0,4,2,1,false,AW_64,2><<<gGrid, 256, SM_64>>>(
        t2, wrc, r_g, r_b, r_out_w, r_out_b, rmap, RMIDc, Cc, Cc);

    // peaks -> centers
    topk_kernel<<<Bn, 1024>>>(out, peaks, centers);

    // bilinear sample + MLP -> per-peak gaussian params
    mlp_kernel<<<Bn * Kk, 128>>>(x, rmap, centers, mlp_w1, mlp_b1, mlp_w2, mlp_b2,
                                 log_alpha, params);

    // gaussian mixture -> attn channel
    gauss_kernel<<<Bn * HWc / 256, 256>>>(params, out);
}